// round 6
// baseline (speedup 1.0000x reference)
#include <cuda_runtime.h>
#include <cuda_bf16.h>
#include <stdint.h>

#define DEVI __device__ __forceinline__

// ---------------- problem sizes ----------------
#define BB 8
#define TT 4096
#define SSZ 256
#define DDIM 512

// ---------------- GEMM tiling ----------------
#define BM 128
#define BN 128
#define BK 64
#define NCH (DDIM / BK)       // 8 k-chunks

#define STRE 72               // padded row stride in bf16 elems
#define ROWB (STRE * 2)       // 144 bytes per smem row
#define TILE_BYTES (BM * ROWB)            // 18432 (A and B tiles equal: 128 rows)
#define OFF_AHI 0
#define OFF_ALO (TILE_BYTES)
#define OFF_BHI (2 * TILE_BYTES)
#define OFF_BLO (3 * TILE_BYTES)
#define STAGE_BYTES (4 * TILE_BYTES)      // 73728
#define SMEM_BYTES (2 * STAGE_BYTES)      // 147456

// ---------------- device scratch (alloc-free) ----------------
__device__ uint4 g_Ahi[(size_t)(BB * TT) * DDIM / 8];
__device__ uint4 g_Alo[(size_t)(BB * TT) * DDIM / 8];
__device__ uint4 g_Bhi[(size_t)(BB * SSZ) * DDIM / 8];
__device__ uint4 g_Blo[(size_t)(BB * SSZ) * DDIM / 8];
__device__ float g_rnx[BB * TT];
__device__ float g_rny[BB * SSZ];

// ---------------- PTX helpers ----------------
DEVI uint32_t smem_u32(const void* p) {
    uint32_t a;
    asm("{ .reg .u64 t; cvta.to.shared.u64 t, %1; cvt.u32.u64 %0, t; }" : "=r"(a) : "l"(p));
    return a;
}

DEVI void cpa16(uint32_t s, const void* g) {
    asm volatile("cp.async.cg.shared.global [%0], [%1], 16;" :: "r"(s), "l"(g));
}
#define CP_COMMIT() asm volatile("cp.async.commit_group;" ::: "memory")
#define CP_WAIT(n)  asm volatile("cp.async.wait_group %0;" :: "n"(n) : "memory")

#define LDSM4(r, addr) \
    asm volatile("ldmatrix.sync.aligned.m8n8.x4.shared.b16 {%0,%1,%2,%3}, [%4];" \
        : "=r"((r)[0]), "=r"((r)[1]), "=r"((r)[2]), "=r"((r)[3]) : "r"(addr))

#define MMA16816(c, a, b0, b1) \
    asm volatile("mma.sync.aligned.m16n8k16.row.col.f32.bf16.bf16.f32 " \
        "{%0,%1,%2,%3}, {%4,%5,%6,%7}, {%8,%9}, {%0,%1,%2,%3};" \
        : "+f"((c)[0]), "+f"((c)[1]), "+f"((c)[2]), "+f"((c)[3]) \
        : "r"((a)[0]), "r"((a)[1]), "r"((a)[2]), "r"((a)[3]), "r"(b0), "r"(b1))

// ---------------- pass 1: per-row reciprocal norm + bf16 hi/lo split ----------------
__global__ void __launch_bounds__(128) split_kernel(const float* __restrict__ x, int isA)
{
    __shared__ float wsum[4];
    const int row = blockIdx.x;
    const int t = threadIdx.x;
    const size_t base = (size_t)row * DDIM + (size_t)t * 4;

    float4 v = *(const float4*)(x + base);
    float ss = v.x * v.x + v.y * v.y + v.z * v.z + v.w * v.w;
    #pragma unroll
    for (int o = 16; o > 0; o >>= 1) ss += __shfl_xor_sync(0xFFFFFFFFu, ss, o);
    if ((t & 31) == 0) wsum[t >> 5] = ss;
    __syncthreads();
    if (t == 0) {
        float tot = wsum[0] + wsum[1] + wsum[2] + wsum[3];
        float* rn = isA ? g_rnx : g_rny;
        rn[row] = 1.0f / fmaxf(sqrtf(tot), 1e-8f);
    }

    __nv_bfloat16* hi = reinterpret_cast<__nv_bfloat16*>(isA ? g_Ahi : g_Bhi);
    __nv_bfloat16* lo = reinterpret_cast<__nv_bfloat16*>(isA ? g_Alo : g_Blo);
    float f[4] = {v.x, v.y, v.z, v.w};
    union { __nv_bfloat162 p[2]; uint2 u; } H, L;
    #pragma unroll
    for (int i = 0; i < 2; ++i) {
        __nv_bfloat16 h0 = __float2bfloat16(f[2 * i + 0]);
        __nv_bfloat16 h1 = __float2bfloat16(f[2 * i + 1]);
        __nv_bfloat16 l0 = __float2bfloat16(f[2 * i + 0] - __bfloat162float(h0));
        __nv_bfloat16 l1 = __float2bfloat16(f[2 * i + 1] - __bfloat162float(h1));
        H.p[i] = __halves2bfloat162(h0, h1);
        L.p[i] = __halves2bfloat162(l0, l1);
    }
    *(uint2*)(hi + base) = H.u;
    *(uint2*)(lo + base) = L.u;
}

// ---------------- pass 2: split-bf16 mma.sync GEMM + scale epilogue ----------------
__global__ void __launch_bounds__(256, 1) gemm_kernel(float* __restrict__ out)
{
    extern __shared__ __align__(16) char smem[];
    const uint32_t sb = smem_u32(smem);

    const int tid  = threadIdx.x;
    const int lane = tid & 31;
    const int wid  = tid >> 5;
    const int bt = blockIdx.z;
    const int m0 = blockIdx.x * BM;
    const int n0 = blockIdx.y * BN;
    const int wm = (wid & 3) * 32;    // warp row base within CTA tile
    const int wn = (wid >> 2) * 64;   // warp col base within CTA tile

    const __nv_bfloat16* Ahi = reinterpret_cast<const __nv_bfloat16*>(g_Ahi);
    const __nv_bfloat16* Alo = reinterpret_cast<const __nv_bfloat16*>(g_Alo);
    const __nv_bfloat16* Bhi = reinterpret_cast<const __nv_bfloat16*>(g_Bhi);
    const __nv_bfloat16* Blo = reinterpret_cast<const __nv_bfloat16*>(g_Blo);

    const size_t aBase = (size_t)(bt * TT + m0) * DDIM;
    const size_t bBase = (size_t)(bt * SSZ + n0) * DDIM;

    // per-thread load mapping: 1024 16B-vectors per tile, 4 iters of 256 threads
    // v = tid + i*256 -> row = v>>3 (0..127), j = v&7 (16B chunk within 128B row)
    float acc[2][8][4];
    #pragma unroll
    for (int mt = 0; mt < 2; ++mt)
        #pragma unroll
        for (int nt = 0; nt < 8; ++nt)
            #pragma unroll
            for (int q = 0; q < 4; ++q) acc[mt][nt][q] = 0.0f;

    auto issue = [&](int stg, int c) {
        const uint32_t sbase = sb + (uint32_t)stg * STAGE_BYTES;
        const int kc = c * BK;
        #pragma unroll
        for (int i = 0; i < 4; ++i) {
            int v = tid + i * 256;
            int r = v >> 3, j = v & 7;
            size_t gofs = (size_t)r * DDIM + kc + j * 8;
            uint32_t so = (uint32_t)r * ROWB + (uint32_t)j * 16;
            cpa16(sbase + OFF_AHI + so, Ahi + aBase + gofs);
            cpa16(sbase + OFF_ALO + so, Alo + aBase + gofs);
            cpa16(sbase + OFF_BHI + so, Bhi + bBase + gofs);
            cpa16(sbase + OFF_BLO + so, Blo + bBase + gofs);
        }
        CP_COMMIT();
    };

    issue(0, 0);

    for (int c = 0; c < NCH; ++c) {
        if (c + 1 < NCH) {
            issue((c + 1) & 1, c + 1);
            CP_WAIT(1);
        } else {
            CP_WAIT(0);
        }
        __syncthreads();

        const uint32_t sbase = sb + (uint32_t)(c & 1) * STAGE_BYTES;
        #pragma unroll
        for (int ks = 0; ks < 4; ++ks) {
            const int k0 = ks * 16;
            // A fragments (hi and lo) for 2 m-tiles
            uint32_t ah[2][4], al[2][4];
            #pragma unroll
            for (int mt = 0; mt < 2; ++mt) {
                uint32_t ad = sbase + OFF_AHI
                            + (uint32_t)(wm + mt * 16 + (lane & 15)) * ROWB
                            + (uint32_t)(k0 * 2) + (uint32_t)((lane >> 4) * 16);
                LDSM4(ah[mt], ad);
                LDSM4(al[mt], ad + (OFF_ALO - OFF_AHI));
            }
            // B fragments in pairs of n-tiles
            #pragma unroll
            for (int p = 0; p < 4; ++p) {
                uint32_t bd = sbase + OFF_BHI
                            + (uint32_t)(wn + p * 16 + (lane & 15)) * ROWB
                            + (uint32_t)(k0 * 2) + (uint32_t)((lane >> 4) * 16);
                uint32_t bh[4], bl[4];
                LDSM4(bh, bd);
                LDSM4(bl, bd + (OFF_BLO - OFF_BHI));
                // reg mapping: {r0,r2} = n-tile 2p, {r1,r3} = n-tile 2p+1
                #pragma unroll
                for (int mt = 0; mt < 2; ++mt) {
                    MMA16816(acc[mt][2 * p + 0], ah[mt], bh[0], bh[2]);
                    MMA16816(acc[mt][2 * p + 0], ah[mt], bl[0], bl[2]);
                    MMA16816(acc[mt][2 * p + 0], al[mt], bh[0], bh[2]);
                    MMA16816(acc[mt][2 * p + 1], ah[mt], bh[1], bh[3]);
                    MMA16816(acc[mt][2 * p + 1], ah[mt], bl[1], bl[3]);
                    MMA16816(acc[mt][2 * p + 1], al[mt], bh[1], bh[3]);
                }
            }
        }
        __syncthreads();
    }

    // ---------------- epilogue: scale by rnx[row] * rny[col] ----------------
    const float* rnx = g_rnx + bt * TT + m0;
    const float* rny = g_rny + bt * SSZ + n0;

    #pragma unroll
    for (int mt = 0; mt < 2; ++mt) {
        const int r0 = wm + mt * 16 + (lane >> 2);
        const float rx0 = rnx[r0];
        const float rx1 = rnx[r0 + 8];
        float* o0 = out + (size_t)(bt * TT + m0 + r0) * SSZ + n0;
        float* o8 = o0 + (size_t)8 * SSZ;
        #pragma unroll
        for (int nt = 0; nt < 8; ++nt) {
            const int cn = wn + nt * 8 + 2 * (lane & 3);
            const float2 ry = *(const float2*)(rny + cn);
            float2 w0, w1;
            w0.x = acc[mt][nt][0] * rx0 * ry.x;
            w0.y = acc[mt][nt][1] * rx0 * ry.y;
            w1.x = acc[mt][nt][2] * rx1 * ry.x;
            w1.y = acc[mt][nt][3] * rx1 * ry.y;
            *(float2*)(o0 + cn) = w0;
            *(float2*)(o8 + cn) = w1;
        }
    }
}

// ---------------- launcher ----------------
extern "C" void kernel_launch(void* const* d_in, const int* in_sizes, int n_in,
                              void* d_out, int out_size)
{
    const float* x = (const float*)d_in[0];   // xs_pad (8,4096,512)
    const float* y = (const float*)d_in[1];   // spk_emb (8,256,512)
    if (n_in >= 2 && in_sizes[0] < in_sizes[1]) {  // robustness vs metadata order
        const float* t = x; x = y; y = t;
    }

    split_kernel<<<BB * TT, 128>>>(x, 1);
    split_kernel<<<BB * SSZ, 128>>>(y, 0);

    cudaFuncSetAttribute(gemm_kernel, cudaFuncAttributeMaxDynamicSharedMemorySize, SMEM_BYTES);
    gemm_kernel<<<dim3(TT / BM, SSZ / BN, BB), 256, SMEM_BYTES>>>((float*)d_out);

    (void)n_in; (void)out_size;
}

// round 12
// speedup vs baseline: 2.3033x; 2.3033x over previous
#include <cuda_runtime.h>
#include <cuda_fp16.h>
#include <stdint.h>

#define DEVI __device__ __forceinline__

// ---------------- problem sizes ----------------
#define BB 8
#define TT 4096
#define SSZ 256
#define DDIM 512

// ---------------- GEMM tiling ----------------
#define BM 128
#define BN 128
#define BK 64
#define NCH (DDIM / BK)       // 8 k-chunks

#define ROWB 144              // 128B of fp16 data + 16B pad (conflict-free ldmatrix)
#define TILE_BYTES (128 * ROWB)           // 18432
#define OFF_A 0
#define OFF_B TILE_BYTES
#define STAGE_BYTES (2 * TILE_BYTES)      // 36864
#define SMEM_BYTES (2 * STAGE_BYTES)      // 73728 -> 2 CTAs/SM fit

// ---------------- device scratch (alloc-free): fp32-normalized fp16 inputs ----
__device__ uint4 g_Xn[(size_t)(BB * TT) * DDIM / 8];   // (8,4096,512) fp16
__device__ uint4 g_Yn[(size_t)(BB * SSZ) * DDIM / 8];  // (8,256,512)  fp16

// ---------------- PTX helpers ----------------
DEVI uint32_t smem_u32(const void* p) {
    uint32_t a;
    asm("{ .reg .u64 t; cvta.to.shared.u64 t, %1; cvt.u32.u64 %0, t; }" : "=r"(a) : "l"(p));
    return a;
}

DEVI void cpa16(uint32_t s, const void* g) {
    asm volatile("cp.async.cg.shared.global [%0], [%1], 16;" :: "r"(s), "l"(g));
}
#define CP_COMMIT() asm volatile("cp.async.commit_group;" ::: "memory")
#define CP_WAIT(n)  asm volatile("cp.async.wait_group %0;" :: "n"(n) : "memory")

#define LDSM4(r, addr) \
    asm volatile("ldmatrix.sync.aligned.m8n8.x4.shared.b16 {%0,%1,%2,%3}, [%4];" \
        : "=r"((r)[0]), "=r"((r)[1]), "=r"((r)[2]), "=r"((r)[3]) : "r"(addr))

// non-volatile: register-only, compiler schedules freely; kept alive by acc uses
#define MMAF16(c, a, b0, b1) \
    asm("mma.sync.aligned.m16n8k16.row.col.f32.f16.f16.f32 " \
        "{%0,%1,%2,%3}, {%4,%5,%6,%7}, {%8,%9}, {%0,%1,%2,%3};" \
        : "+f"((c)[0]), "+f"((c)[1]), "+f"((c)[2]), "+f"((c)[3]) \
        : "r"((a)[0]), "r"((a)[1]), "r"((a)[2]), "r"((a)[3]), "r"(b0), "r"(b1))

// ---------------- pass 1 (fused): fp32 row-norm -> normalized fp16 scratch ----
// One warp per 512-elem row; 8 rows per 256-thread block.
// Rows [0, BB*TT) come from x -> g_Xn; rows [BB*TT, BB*TT+BB*SSZ) from y -> g_Yn.
// Scratch symbols are referenced ONLY in device code (host-side symbol address
// is invalid -- that was the R11 bug).
__global__ void __launch_bounds__(256) norm_kernel(const float* __restrict__ x,
                                                   const float* __restrict__ y)
{
    const int gid  = blockIdx.x * 8 + (threadIdx.x >> 5);
    const int lane = threadIdx.x & 31;

    const float* src;
    __half* dst;
    if (gid < BB * TT) {
        src = x + (size_t)gid * DDIM;
        dst = reinterpret_cast<__half*>(g_Xn) + (size_t)gid * DDIM;
    } else {
        const int r = gid - BB * TT;
        src = y + (size_t)r * DDIM;
        dst = reinterpret_cast<__half*>(g_Yn) + (size_t)r * DDIM;
    }

    float4 v[4];
    float ss = 0.0f;
    #pragma unroll
    for (int c = 0; c < 4; ++c) {
        v[c] = *(const float4*)(src + c * 128 + lane * 4);
        ss += v[c].x * v[c].x + v[c].y * v[c].y + v[c].z * v[c].z + v[c].w * v[c].w;
    }
    #pragma unroll
    for (int o = 16; o > 0; o >>= 1) ss += __shfl_xor_sync(0xFFFFFFFFu, ss, o);
    const float rn = 1.0f / fmaxf(sqrtf(ss), 1e-8f);

    #pragma unroll
    for (int c = 0; c < 4; ++c) {
        union { __half2 h[2]; uint2 u; } P;
        P.h[0] = __floats2half2_rn(v[c].x * rn, v[c].y * rn);
        P.h[1] = __floats2half2_rn(v[c].z * rn, v[c].w * rn);
        *(uint2*)(dst + c * 128 + lane * 4) = P.u;
    }
}

// ---------------- pass 2: fp16 mma.sync GEMM (inputs pre-normalized) ----------
__global__ void __launch_bounds__(256, 2) gemm_kernel(float* __restrict__ out)
{
    extern __shared__ __align__(16) char smem[];
    const uint32_t sb = smem_u32(smem);

    const int tid  = threadIdx.x;
    const int lane = tid & 31;
    const int wid  = tid >> 5;
    const int bt = blockIdx.z;
    const int m0 = blockIdx.x * BM;
    const int n0 = blockIdx.y * BN;
    const int wm = (wid & 3) * 32;    // warp row base (4 warps over M)
    const int wn = (wid >> 2) * 64;   // warp col base (2 warps over N)

    const __half* X = reinterpret_cast<const __half*>(g_Xn);
    const __half* Y = reinterpret_cast<const __half*>(g_Yn);
    const size_t aBase = (size_t)(bt * TT + m0) * DDIM;
    const size_t bBase = (size_t)(bt * SSZ + n0) * DDIM;

    float acc[2][8][4];
    #pragma unroll
    for (int mt = 0; mt < 2; ++mt)
        #pragma unroll
        for (int nt = 0; nt < 8; ++nt)
            #pragma unroll
            for (int q = 0; q < 4; ++q) acc[mt][nt][q] = 0.0f;

    // per stage: A tile 1024 x 16B vectors + B tile 1024 -> 8 cp.async/thread
    auto issue = [&](int stg, int c) {
        const uint32_t sbase = sb + (uint32_t)stg * STAGE_BYTES;
        const int kc = c * BK;
        #pragma unroll
        for (int i = 0; i < 4; ++i) {
            int v = tid + i * 256;
            int r = v >> 3, j = v & 7;
            size_t gofs = (size_t)r * DDIM + kc + j * 8;
            uint32_t so = (uint32_t)r * ROWB + (uint32_t)j * 16;
            cpa16(sbase + OFF_A + so, X + aBase + gofs);
            cpa16(sbase + OFF_B + so, Y + bBase + gofs);
        }
        CP_COMMIT();
    };

    issue(0, 0);

    for (int c = 0; c < NCH; ++c) {
        if (c + 1 < NCH) {
            issue((c + 1) & 1, c + 1);
            CP_WAIT(1);
        } else {
            CP_WAIT(0);
        }
        __syncthreads();

        const uint32_t sbase = sb + (uint32_t)(c & 1) * STAGE_BYTES;
        #pragma unroll
        for (int ks = 0; ks < 4; ++ks) {
            const uint32_t kb = (uint32_t)(ks * 32) + (uint32_t)((lane >> 4) * 16);
            uint32_t a[2][4];
            #pragma unroll
            for (int mt = 0; mt < 2; ++mt) {
                uint32_t ad = sbase + OFF_A
                            + (uint32_t)(wm + mt * 16 + (lane & 15)) * ROWB + kb;
                LDSM4(a[mt], ad);
            }
            uint32_t b[4][4];
            #pragma unroll
            for (int p = 0; p < 4; ++p) {
                uint32_t bd = sbase + OFF_B
                            + (uint32_t)(wn + p * 16 + (lane & 15)) * ROWB + kb;
                LDSM4(b[p], bd);
            }
            // 16 MMAs, all distinct accumulators -> no RAW chains
            #pragma unroll
            for (int p = 0; p < 4; ++p)
                #pragma unroll
                for (int mt = 0; mt < 2; ++mt) {
                    MMAF16(acc[mt][2 * p + 0], a[mt], b[p][0], b[p][2]);
                    MMAF16(acc[mt][2 * p + 1], a[mt], b[p][1], b[p][3]);
                }
        }
        __syncthreads();
    }

    // ---------------- epilogue: direct store (inputs were pre-normalized) ----
    #pragma unroll
    for (int mt = 0; mt < 2; ++mt) {
        const int r0 = wm + mt * 16 + (lane >> 2);
        float* o0 = out + (size_t)(bt * TT + m0 + r0) * SSZ + n0;
        float* o8 = o0 + (size_t)8 * SSZ;
        #pragma unroll
        for (int nt = 0; nt < 8; ++nt) {
            const int cn = wn + nt * 8 + 2 * (lane & 3);
            *(float2*)(o0 + cn) = make_float2(acc[mt][nt][0], acc[mt][nt][1]);
            *(float2*)(o8 + cn) = make_float2(acc[mt][nt][2], acc[mt][nt][3]);
        }
    }
}

// ---------------- launcher ----------------
extern "C" void kernel_launch(void* const* d_in, const int* in_sizes, int n_in,
                              void* d_out, int out_size)
{
    const float* x = (const float*)d_in[0];   // xs_pad (8,4096,512)
    const float* y = (const float*)d_in[1];   // spk_emb (8,256,512)
    if (n_in >= 2 && in_sizes[0] < in_sizes[1]) {  // robustness vs metadata order
        const float* t = x; x = y; y = t;
    }

    // fused norm pass: 32768 X-rows + 2048 Y-rows, 8 rows per block
    norm_kernel<<<(BB * TT + BB * SSZ) / 8, 256>>>(x, y);

    cudaFuncSetAttribute(gemm_kernel, cudaFuncAttributeMaxDynamicSharedMemorySize, SMEM_BYTES);
    gemm_kernel<<<dim3(TT / BM, SSZ / BN, BB), 256, SMEM_BYTES>>>((float*)d_out);

    (void)n_in; (void)out_size;
}

// round 13
// speedup vs baseline: 2.3889x; 1.0371x over previous
#include <cuda_runtime.h>
#include <cuda_fp16.h>
#include <stdint.h>

#define DEVI __device__ __forceinline__

// ---------------- problem sizes ----------------
#define BB 8
#define TT 4096
#define SSZ 256
#define DDIM 512

// ---------------- GEMM tiling ----------------
#define BM 64
#define BN 128
#define BK 64
#define NCH (DDIM / BK)       // 8 k-chunks

#define ROWB 144              // 128B of fp16 data + 16B pad (conflict-free ldmatrix)
#define A_ROWS BM
#define B_ROWS BN
#define OFF_A 0
#define OFF_B (A_ROWS * ROWB)                       // 9216
#define STAGE_BYTES ((A_ROWS + B_ROWS) * ROWB)      // 27648
#define SMEM_BYTES (2 * STAGE_BYTES)                // 55296 -> 4 CTAs/SM

// ---------------- device scratch (alloc-free): fp32-normalized fp16 inputs ----
__device__ uint4 g_Xn[(size_t)(BB * TT) * DDIM / 8];   // (8,4096,512) fp16
__device__ uint4 g_Yn[(size_t)(BB * SSZ) * DDIM / 8];  // (8,256,512)  fp16

// ---------------- PTX helpers ----------------
DEVI uint32_t smem_u32(const void* p) {
    uint32_t a;
    asm("{ .reg .u64 t; cvta.to.shared.u64 t, %1; cvt.u32.u64 %0, t; }" : "=r"(a) : "l"(p));
    return a;
}

DEVI void cpa16(uint32_t s, const void* g) {
    asm volatile("cp.async.cg.shared.global [%0], [%1], 16;" :: "r"(s), "l"(g));
}
#define CP_COMMIT() asm volatile("cp.async.commit_group;" ::: "memory")
#define CP_WAIT(n)  asm volatile("cp.async.wait_group %0;" :: "n"(n) : "memory")

#define LDSM4(r, addr) \
    asm volatile("ldmatrix.sync.aligned.m8n8.x4.shared.b16 {%0,%1,%2,%3}, [%4];" \
        : "=r"((r)[0]), "=r"((r)[1]), "=r"((r)[2]), "=r"((r)[3]) : "r"(addr))

// non-volatile: register-only, compiler schedules freely; kept alive by acc uses
#define MMAF16(c, a, b0, b1) \
    asm("mma.sync.aligned.m16n8k16.row.col.f32.f16.f16.f32 " \
        "{%0,%1,%2,%3}, {%4,%5,%6,%7}, {%8,%9}, {%0,%1,%2,%3};" \
        : "+f"((c)[0]), "+f"((c)[1]), "+f"((c)[2]), "+f"((c)[3]) \
        : "r"((a)[0]), "r"((a)[1]), "r"((a)[2]), "r"((a)[3]), "r"(b0), "r"(b1))

// ---------------- pass 1 (fused): fp32 row-norm -> normalized fp16 scratch ----
// One warp per 512-elem row; 8 rows per 256-thread block.
// Rows [0, BB*TT) from x -> g_Xn; rows beyond from y -> g_Yn.
// Scratch symbols referenced ONLY in device code (host symbol address invalid).
__global__ void __launch_bounds__(256) norm_kernel(const float* __restrict__ x,
                                                   const float* __restrict__ y)
{
    const int gid  = blockIdx.x * 8 + (threadIdx.x >> 5);
    const int lane = threadIdx.x & 31;

    const float* src;
    __half* dst;
    if (gid < BB * TT) {
        src = x + (size_t)gid * DDIM;
        dst = reinterpret_cast<__half*>(g_Xn) + (size_t)gid * DDIM;
    } else {
        const int r = gid - BB * TT;
        src = y + (size_t)r * DDIM;
        dst = reinterpret_cast<__half*>(g_Yn) + (size_t)r * DDIM;
    }

    float4 v[4];
    float ss = 0.0f;
    #pragma unroll
    for (int c = 0; c < 4; ++c) {
        v[c] = *(const float4*)(src + c * 128 + lane * 4);
        ss += v[c].x * v[c].x + v[c].y * v[c].y + v[c].z * v[c].z + v[c].w * v[c].w;
    }
    #pragma unroll
    for (int o = 16; o > 0; o >>= 1) ss += __shfl_xor_sync(0xFFFFFFFFu, ss, o);
    const float rn = 1.0f / fmaxf(sqrtf(ss), 1e-8f);

    #pragma unroll
    for (int c = 0; c < 4; ++c) {
        union { __half2 h[2]; uint2 u; } P;
        P.h[0] = __floats2half2_rn(v[c].x * rn, v[c].y * rn);
        P.h[1] = __floats2half2_rn(v[c].z * rn, v[c].w * rn);
        *(uint2*)(dst + c * 128 + lane * 4) = P.u;
    }
}

// ---------------- pass 2: fp16 mma.sync GEMM, 4 CTAs/SM ----------------------
__global__ void __launch_bounds__(128, 4) gemm_kernel(float* __restrict__ out)
{
    extern __shared__ __align__(16) char smem[];
    const uint32_t sb = smem_u32(smem);

    const int tid  = threadIdx.x;
    const int lane = tid & 31;
    const int wid  = tid >> 5;        // 0..3
    const int bt = blockIdx.z;
    const int m0 = blockIdx.x * BM;
    const int n0 = blockIdx.y * BN;
    const int wm = (wid & 1) * 32;    // 2 warps over M
    const int wn = (wid >> 1) * 64;   // 2 warps over N

    const __half* X = reinterpret_cast<const __half*>(g_Xn);
    const __half* Y = reinterpret_cast<const __half*>(g_Yn);
    const size_t aBase = (size_t)(bt * TT + m0) * DDIM;
    const size_t bBase = (size_t)(bt * SSZ + n0) * DDIM;

    float acc[2][8][4];
    #pragma unroll
    for (int mt = 0; mt < 2; ++mt)
        #pragma unroll
        for (int nt = 0; nt < 8; ++nt)
            #pragma unroll
            for (int q = 0; q < 4; ++q) acc[mt][nt][q] = 0.0f;

    // per stage: A 64 rows (512 vecs) + B 128 rows (1024 vecs); 128 threads
    // -> A: 4 vec/thread, B: 8 vec/thread
    auto issue = [&](int stg, int c) {
        const uint32_t sbase = sb + (uint32_t)stg * STAGE_BYTES;
        const int kc = c * BK;
        #pragma unroll
        for (int i = 0; i < 4; ++i) {
            int v = tid + i * 128;
            int r = v >> 3, j = v & 7;
            cpa16(sbase + OFF_A + (uint32_t)r * ROWB + (uint32_t)j * 16,
                  X + aBase + (size_t)r * DDIM + kc + j * 8);
        }
        #pragma unroll
        for (int i = 0; i < 8; ++i) {
            int v = tid + i * 128;
            int r = v >> 3, j = v & 7;
            cpa16(sbase + OFF_B + (uint32_t)r * ROWB + (uint32_t)j * 16,
                  Y + bBase + (size_t)r * DDIM + kc + j * 8);
        }
        CP_COMMIT();
    };

    issue(0, 0);

    for (int c = 0; c < NCH; ++c) {
        if (c + 1 < NCH) {
            issue((c + 1) & 1, c + 1);
            CP_WAIT(1);
        } else {
            CP_WAIT(0);
        }
        __syncthreads();

        const uint32_t sbase = sb + (uint32_t)(c & 1) * STAGE_BYTES;
        #pragma unroll
        for (int ks = 0; ks < 4; ++ks) {
            const uint32_t kb = (uint32_t)(ks * 32) + (uint32_t)((lane >> 4) * 16);
            uint32_t a[2][4];
            #pragma unroll
            for (int mt = 0; mt < 2; ++mt) {
                uint32_t ad = sbase + OFF_A
                            + (uint32_t)(wm + mt * 16 + (lane & 15)) * ROWB + kb;
                LDSM4(a[mt], ad);
            }
            uint32_t b[4][4];
            #pragma unroll
            for (int p = 0; p < 4; ++p) {
                uint32_t bd = sbase + OFF_B
                            + (uint32_t)(wn + p * 16 + (lane & 15)) * ROWB + kb;
                LDSM4(b[p], bd);
            }
            // 16 MMAs, all distinct accumulators -> no RAW chains
            #pragma unroll
            for (int p = 0; p < 4; ++p)
                #pragma unroll
                for (int mt = 0; mt < 2; ++mt) {
                    MMAF16(acc[mt][2 * p + 0], a[mt], b[p][0], b[p][2]);
                    MMAF16(acc[mt][2 * p + 1], a[mt], b[p][1], b[p][3]);
                }
        }
        __syncthreads();
    }

    // ---------------- epilogue: direct store (inputs were pre-normalized) ----
    #pragma unroll
    for (int mt = 0; mt < 2; ++mt) {
        const int r0 = wm + mt * 16 + (lane >> 2);
        float* o0 = out + (size_t)(bt * TT + m0 + r0) * SSZ + n0;
        float* o8 = o0 + (size_t)8 * SSZ;
        #pragma unroll
        for (int nt = 0; nt < 8; ++nt) {
            const int cn = wn + nt * 8 + 2 * (lane & 3);
            *(float2*)(o0 + cn) = make_float2(acc[mt][nt][0], acc[mt][nt][1]);
            *(float2*)(o8 + cn) = make_float2(acc[mt][nt][2], acc[mt][nt][3]);
        }
    }
}

// ---------------- launcher ----------------
extern "C" void kernel_launch(void* const* d_in, const int* in_sizes, int n_in,
                              void* d_out, int out_size)
{
    const float* x = (const float*)d_in[0];   // xs_pad (8,4096,512)
    const float* y = (const float*)d_in[1];   // spk_emb (8,256,512)
    if (n_in >= 2 && in_sizes[0] < in_sizes[1]) {  // robustness vs metadata order
        const float* t = x; x = y; y = t;
    }

    // fused norm pass: 32768 X-rows + 2048 Y-rows, 8 rows per block
    norm_kernel<<<(BB * TT + BB * SSZ) / 8, 256>>>(x, y);

    cudaFuncSetAttribute(gemm_kernel, cudaFuncAttributeMaxDynamicSharedMemorySize, SMEM_BYTES);
    gemm_kernel<<<dim3(TT / BM, SSZ / BN, BB), 128, SMEM_BYTES>>>((float*)d_out);

    (void)n_in; (void)out_size;
}

// round 14
// speedup vs baseline: 2.4718x; 1.0347x over previous
#include <cuda_runtime.h>
#include <cuda_fp16.h>
#include <stdint.h>

#define DEVI __device__ __forceinline__

// ---------------- problem sizes ----------------
#define BB 8
#define TT 4096
#define SSZ 256
#define DDIM 512

// ---------------- GEMM tiling ----------------
#define BM 64
#define BN 128
#define BK 64
#define NCH (DDIM / BK)       // 8 k-chunks

#define ROWB 144              // 128B fp16 data + 16B pad (conflict-free ldmatrix)
#define OFF_A 0
#define OFF_B (BM * ROWB)                           // 9216
#define STAGE_BYTES ((BM + BN) * ROWB)              // 27648
#define SMEM_BYTES (2 * STAGE_BYTES)                // 55296 -> 3 CTAs/SM (smem)

// ---------------- device scratch (alloc-free): fp32-normalized fp16 inputs ----
__device__ uint4 g_Xn[(size_t)(BB * TT) * DDIM / 8];   // (8,4096,512) fp16
__device__ uint4 g_Yn[(size_t)(BB * SSZ) * DDIM / 8];  // (8,256,512)  fp16

// ---------------- PTX helpers ----------------
DEVI uint32_t smem_u32(const void* p) {
    uint32_t a;
    asm("{ .reg .u64 t; cvta.to.shared.u64 t, %1; cvt.u32.u64 %0, t; }" : "=r"(a) : "l"(p));
    return a;
}

DEVI void cpa16(uint32_t s, const void* g) {
    asm volatile("cp.async.cg.shared.global [%0], [%1], 16;" :: "r"(s), "l"(g));
}
#define CP_COMMIT() asm volatile("cp.async.commit_group;" ::: "memory")
#define CP_WAIT(n)  asm volatile("cp.async.wait_group %0;" :: "n"(n) : "memory")

#define LDSM4(r, addr) \
    asm volatile("ldmatrix.sync.aligned.m8n8.x4.shared.b16 {%0,%1,%2,%3}, [%4];" \
        : "=r"((r)[0]), "=r"((r)[1]), "=r"((r)[2]), "=r"((r)[3]) : "r"(addr))

// non-volatile: register-only, compiler schedules freely; kept alive by acc uses
#define MMAF16(c, a, b0, b1) \
    asm("mma.sync.aligned.m16n8k16.row.col.f32.f16.f16.f32 " \
        "{%0,%1,%2,%3}, {%4,%5,%6,%7}, {%8,%9}, {%0,%1,%2,%3};" \
        : "+f"((c)[0]), "+f"((c)[1]), "+f"((c)[2]), "+f"((c)[3]) \
        : "r"((a)[0]), "r"((a)[1]), "r"((a)[2]), "r"((a)[3]), "r"(b0), "r"(b1))

// ---------------- pass 1 (fused): fp32 row-norm -> normalized fp16 scratch ----
// One warp per 512-elem row; 8 rows per 256-thread block.
// Rows [0, BB*TT) from x -> g_Xn; rows beyond from y -> g_Yn.
// Scratch symbols referenced ONLY in device code (host symbol address invalid).
__global__ void __launch_bounds__(256) norm_kernel(const float* __restrict__ x,
                                                   const float* __restrict__ y)
{
    const int gid  = blockIdx.x * 8 + (threadIdx.x >> 5);
    const int lane = threadIdx.x & 31;

    const float* src;
    __half* dst;
    if (gid < BB * TT) {
        src = x + (size_t)gid * DDIM;
        dst = reinterpret_cast<__half*>(g_Xn) + (size_t)gid * DDIM;
    } else {
        const int r = gid - BB * TT;
        src = y + (size_t)r * DDIM;
        dst = reinterpret_cast<__half*>(g_Yn) + (size_t)r * DDIM;
    }

    float4 v[4];
    float ss = 0.0f;
    #pragma unroll
    for (int c = 0; c < 4; ++c) {
        v[c] = *(const float4*)(src + c * 128 + lane * 4);
        ss += v[c].x * v[c].x + v[c].y * v[c].y + v[c].z * v[c].z + v[c].w * v[c].w;
    }
    #pragma unroll
    for (int o = 16; o > 0; o >>= 1) ss += __shfl_xor_sync(0xFFFFFFFFu, ss, o);
    const float rn = 1.0f / fmaxf(sqrtf(ss), 1e-8f);

    #pragma unroll
    for (int c = 0; c < 4; ++c) {
        union { __half2 h[2]; uint2 u; } P;
        P.h[0] = __floats2half2_rn(v[c].x * rn, v[c].y * rn);
        P.h[1] = __floats2half2_rn(v[c].z * rn, v[c].w * rn);
        *(uint2*)(dst + c * 128 + lane * 4) = P.u;
    }
}

// ---------------- pass 2: fp16 mma.sync GEMM, 8 warps (32x32 tiles), 3 CTA/SM -
__global__ void __launch_bounds__(256, 3) gemm_kernel(float* __restrict__ out)
{
    extern __shared__ __align__(16) char smem[];
    const uint32_t sb = smem_u32(smem);

    const int tid  = threadIdx.x;
    const int lane = tid & 31;
    const int wid  = tid >> 5;        // 0..7
    const int bt = blockIdx.z;
    const int m0 = blockIdx.x * BM;
    const int n0 = blockIdx.y * BN;
    const int wm = (wid & 1) * 32;    // 2 warps over M
    const int wn = (wid >> 1) * 32;   // 4 warps over N

    const __half* X = reinterpret_cast<const __half*>(g_Xn);
    const __half* Y = reinterpret_cast<const __half*>(g_Yn);
    const size_t aBase = (size_t)(bt * TT + m0) * DDIM;
    const size_t bBase = (size_t)(bt * SSZ + n0) * DDIM;

    float acc[2][4][4];
    #pragma unroll
    for (int mt = 0; mt < 2; ++mt)
        #pragma unroll
        for (int nt = 0; nt < 4; ++nt)
            #pragma unroll
            for (int q = 0; q < 4; ++q) acc[mt][nt][q] = 0.0f;

    // per stage: A 64 rows (512 16B-vecs) + B 128 rows (1024 vecs); 256 threads
    auto issue = [&](int stg, int c) {
        const uint32_t sbase = sb + (uint32_t)stg * STAGE_BYTES;
        const int kc = c * BK;
        #pragma unroll
        for (int i = 0; i < 2; ++i) {
            int v = tid + i * 256;
            int r = v >> 3, j = v & 7;
            cpa16(sbase + OFF_A + (uint32_t)r * ROWB + (uint32_t)j * 16,
                  X + aBase + (size_t)r * DDIM + kc + j * 8);
        }
        #pragma unroll
        for (int i = 0; i < 4; ++i) {
            int v = tid + i * 256;
            int r = v >> 3, j = v & 7;
            cpa16(sbase + OFF_B + (uint32_t)r * ROWB + (uint32_t)j * 16,
                  Y + bBase + (size_t)r * DDIM + kc + j * 8);
        }
        CP_COMMIT();
    };

    issue(0, 0);

    for (int c = 0; c < NCH; ++c) {
        CP_WAIT(0);
        __syncthreads();
        // single sync per chunk: writes for chunk c+1 (stage (c+1)&1) are
        // issued only after all warps finished reading that stage (chunk c-1)
        if (c + 1 < NCH) issue((c + 1) & 1, c + 1);

        const uint32_t sbase = sb + (uint32_t)(c & 1) * STAGE_BYTES;
        #pragma unroll
        for (int ks = 0; ks < 4; ++ks) {
            const uint32_t kb = (uint32_t)(ks * 32) + (uint32_t)((lane >> 4) * 16);
            uint32_t a[2][4];
            #pragma unroll
            for (int mt = 0; mt < 2; ++mt) {
                uint32_t ad = sbase + OFF_A
                            + (uint32_t)(wm + mt * 16 + (lane & 15)) * ROWB + kb;
                LDSM4(a[mt], ad);
            }
            uint32_t b[2][4];
            #pragma unroll
            for (int p = 0; p < 2; ++p) {
                uint32_t bd = sbase + OFF_B
                            + (uint32_t)(wn + p * 16 + (lane & 15)) * ROWB + kb;
                LDSM4(b[p], bd);
            }
            // 8 MMAs, all distinct accumulators -> no RAW chains
            #pragma unroll
            for (int p = 0; p < 2; ++p)
                #pragma unroll
                for (int mt = 0; mt < 2; ++mt) {
                    MMAF16(acc[mt][2 * p + 0], a[mt], b[p][0], b[p][2]);
                    MMAF16(acc[mt][2 * p + 1], a[mt], b[p][1], b[p][3]);
                }
        }
    }

    // ---------------- epilogue: direct store (inputs were pre-normalized) ----
    #pragma unroll
    for (int mt = 0; mt < 2; ++mt) {
        const int r0 = wm + mt * 16 + (lane >> 2);
        float* o0 = out + (size_t)(bt * TT + m0 + r0) * SSZ + n0;
        float* o8 = o0 + (size_t)8 * SSZ;
        #pragma unroll
        for (int nt = 0; nt < 4; ++nt) {
            const int cn = wn + nt * 8 + 2 * (lane & 3);
            *(float2*)(o0 + cn) = make_float2(acc[mt][nt][0], acc[mt][nt][1]);
            *(float2*)(o8 + cn) = make_float2(acc[mt][nt][2], acc[mt][nt][3]);
        }
    }
}

// ---------------- launcher ----------------
extern "C" void kernel_launch(void* const* d_in, const int* in_sizes, int n_in,
                              void* d_out, int out_size)
{
    const float* x = (const float*)d_in[0];   // xs_pad (8,4096,512)
    const float* y = (const float*)d_in[1];   // spk_emb (8,256,512)
    if (n_in >= 2 && in_sizes[0] < in_sizes[1]) {  // robustness vs metadata order
        const float* t = x; x = y; y = t;
    }

    // fused norm pass: 32768 X-rows + 2048 Y-rows, 8 rows per block
    norm_kernel<<<(BB * TT + BB * SSZ) / 8, 256>>>(x, y);

    cudaFuncSetAttribute(gemm_kernel, cudaFuncAttributeMaxDynamicSharedMemorySize, SMEM_BYTES);
    gemm_kernel<<<dim3(TT / BM, SSZ / BN, BB), 256, SMEM_BYTES>>>((float*)d_out);

    (void)n_in; (void)out_size;
}